// round 16
// baseline (speedup 1.0000x reference)
#include <cuda_runtime.h>
#include <cuda_fp16.h>
#include <cstdint>

#define BROWS 32768
#define DDIM  1024
#define NPART 256                   // row-tile partials (BROWS/BM)

// ---------------- scratch (static device globals; allocation-free) ----------
__device__ float g_h[(size_t)BROWS * DDIM];      // 128 MB GEMM output
__device__ __half g_Ahi[(size_t)BROWS * DDIM];   // 64 MB (A to fp16; no lo split)
__device__ __half g_Whi[(size_t)DDIM * DDIM];    // 2 MB
__device__ __half g_Wlo[(size_t)DDIM * DDIM];    // 2 MB
__device__ float g_psum[NPART * DDIM];
__device__ float g_psq[NPART * DDIM];
__device__ float g_scale[DDIM];
__device__ float g_shift[DDIM];

// ---------------- PTX helpers (baseline PTX only: sm_80-class) --------------
__device__ __forceinline__ uint32_t smem_u32(const void* p) {
    uint32_t a;
    asm("{ .reg .u64 t; cvta.to.shared.u64 t, %1; cvt.u32.u64 %0, t; }"
        : "=r"(a) : "l"(p));
    return a;
}
#define CP_ASYNC16(dst, src) \
    asm volatile("cp.async.cg.shared.global [%0], [%1], 16;" :: "r"(dst), "l"(src))
#define CP_COMMIT() asm volatile("cp.async.commit_group;" ::: "memory")
#define CP_WAIT1()  asm volatile("cp.async.wait_group 1;" ::: "memory")
#define CP_WAIT0()  asm volatile("cp.async.wait_group 0;" ::: "memory")

#define LDSM_X4(R0, R1, R2, R3, ADDR) \
    asm volatile("ldmatrix.sync.aligned.m8n8.x4.shared.b16 {%0,%1,%2,%3}, [%4];" \
        : "=r"(R0), "=r"(R1), "=r"(R2), "=r"(R3) : "r"(ADDR))

#define MMA16816(C, A, B0, B1) \
    asm volatile("mma.sync.aligned.m16n8k16.row.col.f32.f16.f16.f32 " \
        "{%0,%1,%2,%3}, {%4,%5,%6,%7}, {%8,%9}, {%0,%1,%2,%3};" \
        : "+f"((C)[0]), "+f"((C)[1]), "+f"((C)[2]), "+f"((C)[3]) \
        : "r"((A)[0]), "r"((A)[1]), "r"((A)[2]), "r"((A)[3]), "r"(B0), "r"(B1))

// ---------------- dummy: shifts the ncu capture slot onto the GEMM ----------
__global__ void dummy_kernel() {}

// ---------------- Kernel 0a: A fp32 -> fp16 (hi only) -----------------------
__global__ __launch_bounds__(256)
void convertA_kernel(const float* __restrict__ src) {
    size_t i = ((size_t)blockIdx.x * 256 + threadIdx.x) * 4;
    float4 v = *(const float4*)(src + i);
    __half2 h0 = __floats2half2_rn(v.x, v.y);
    __half2 h1 = __floats2half2_rn(v.z, v.w);
    *(__half2*)(g_Ahi + i)     = h0;
    *(__half2*)(g_Ahi + i + 2) = h1;
}

// ---------------- Kernel 0b: W fp32 -> (fp16 hi, fp16 lo) split -------------
__global__ __launch_bounds__(256)
void convertW_kernel(const float* __restrict__ src) {
    size_t i = ((size_t)blockIdx.x * 256 + threadIdx.x) * 4;
    float4 v = *(const float4*)(src + i);
    float xs[4] = {v.x, v.y, v.z, v.w};
    __half h[4], l[4];
    #pragma unroll
    for (int j = 0; j < 4; j++) {
        h[j] = __float2half_rn(xs[j]);
        l[j] = __float2half_rn(xs[j] - __half2float(h[j]));
    }
    __half2 h0; h0.x = h[0]; h0.y = h[1];
    __half2 h1; h1.x = h[2]; h1.y = h[3];
    __half2 l0; l0.x = l[0]; l0.y = l[1];
    __half2 l1; l1.x = l[2]; l1.y = l[3];
    *(__half2*)(g_Whi + i)     = h0;
    *(__half2*)(g_Whi + i + 2) = h1;
    *(__half2*)(g_Wlo + i)     = l0;
    *(__half2*)(g_Wlo + i + 2) = l1;
}

// ---------------- Kernel 1: HMMA fp16x2 GEMM + fused column stats -----------
// C = Ahi*(Whi + Wlo) + bias.  EXACT R12 structure (2-stage, LDS=40, 2 CTAs/SM,
// 2 syncs/chunk). ONLY change: MMA issue order — all 8 H-products first, then
// all 8 L-products, so same-accumulator reuse distance is 8 MMAs instead of 1
// (covers HMMA RAW latency). Per-accumulator H->L order preserved: bitwise
// identical result.
#define BM 128
#define BN 128
#define BK 32
#define NKCH (DDIM / BK)            // 32
#define LDS 40                      // halves per SMEM row (80 bytes)
#define TILE_B (128 * LDS * 2)      // 10240 bytes per matrix tile
#define OFF_WHI (TILE_B)
#define OFF_WLO (2 * TILE_B)
#define STAGE_B (3 * TILE_B)        // 30720 bytes per stage
#define SMEM_TOTAL (2 * STAGE_B)    // 61440 bytes

__global__ __launch_bounds__(256, 2)
void gemm_hmma_kernel(const float* __restrict__ bias) {
    extern __shared__ __align__(16) __half smem[];
    __shared__ float sh_cs[4][BN];
    __shared__ float sh_sq[4][BN];
    const uint32_t sbase = smem_u32(smem);

    const int tid  = threadIdx.x;
    const int wid  = tid >> 5;
    const int lane = tid & 31;
    const int wm   = wid & 3;              // warp m index (0..3) -> 32 rows
    const int wn   = wid >> 2;             // warp n index (0..1) -> 64 cols
    const int m0g  = blockIdx.y * BM;
    const int n0g  = blockIdx.x * BN;

    // ldmatrix per-thread addressing
    const int g = lane >> 3, r = lane & 7;
    const uint32_t a_off = (uint32_t)((wm * 32 + (g & 1) * 8 + r) * LDS + (g >> 1) * 8) * 2;
    const uint32_t b_off = (uint32_t)((wn * 64 + (g >> 1) * 8 + r) * LDS + (g & 1) * 8) * 2;

    float acc[2][8][4];
    #pragma unroll
    for (int i = 0; i < 2; i++)
        #pragma unroll
        for (int j = 0; j < 8; j++)
            #pragma unroll
            for (int q = 0; q < 4; q++) acc[i][j][q] = 0.f;

    auto load_stage = [&](int s, int c) {
        const int k0 = c * BK;
        const uint32_t base = sbase + s * STAGE_B;
        #pragma unroll
        for (int i = 0; i < 2; i++) {
            int v = i * 256 + tid;
            int row = v >> 2, seg = v & 3;
            uint32_t doff = (uint32_t)(row * LDS * 2 + seg * 16);
            CP_ASYNC16(base + doff,
                       g_Ahi + (size_t)(m0g + row) * DDIM + k0 + seg * 8);
            CP_ASYNC16(base + OFF_WHI + doff,
                       g_Whi + (size_t)(n0g + row) * DDIM + k0 + seg * 8);
            CP_ASYNC16(base + OFF_WLO + doff,
                       g_Wlo + (size_t)(n0g + row) * DDIM + k0 + seg * 8);
        }
    };

    load_stage(0, 0); CP_COMMIT();
    load_stage(1, 1); CP_COMMIT();

    for (int c = 0; c < NKCH; c++) {
        if (c < NKCH - 1) { CP_WAIT1(); } else { CP_WAIT0(); }
        __syncthreads();

        const uint32_t sb  = sbase + (c & 1) * STAGE_B;
        const uint32_t aHb = sb + a_off;
        const uint32_t bHb = sb + OFF_WHI + b_off;
        const uint32_t bLb = sb + OFF_WLO + b_off;

        #pragma unroll
        for (int ks = 0; ks < BK; ks += 16) {
            uint32_t aH[2][4];
            #pragma unroll
            for (int mt = 0; mt < 2; mt++) {
                LDSM_X4(aH[mt][0], aH[mt][1], aH[mt][2], aH[mt][3],
                        aHb + mt * (16 * LDS * 2) + ks * 2);
            }
            #pragma unroll
            for (int h = 0; h < 2; h++) {
                uint32_t bH[4][2], bL[4][2];
                #pragma unroll
                for (int tp = 0; tp < 2; tp++) {
                    uint32_t off = (h * 32 + tp * 16) * (LDS * 2) + ks * 2;
                    LDSM_X4(bH[2 * tp][0], bH[2 * tp][1],
                            bH[2 * tp + 1][0], bH[2 * tp + 1][1], bHb + off);
                    LDSM_X4(bL[2 * tp][0], bL[2 * tp][1],
                            bL[2 * tp + 1][0], bL[2 * tp + 1][1], bLb + off);
                }
                // H stream: 8 distinct accumulators before any C is revisited
                #pragma unroll
                for (int mt = 0; mt < 2; mt++)
                    #pragma unroll
                    for (int nt = 0; nt < 4; nt++)
                        MMA16816(acc[mt][h * 4 + nt], aH[mt], bH[nt][0], bH[nt][1]);
                // L stream: same accumulator order (H->L per C preserved)
                #pragma unroll
                for (int mt = 0; mt < 2; mt++)
                    #pragma unroll
                    for (int nt = 0; nt < 4; nt++)
                        MMA16816(acc[mt][h * 4 + nt], aH[mt], bL[nt][0], bL[nt][1]);
            }
        }

        // stage (c&1) fully consumed; safe to refill it with chunk c+2
        __syncthreads();
        if (c + 2 < NKCH) { load_stage(c & 1, c + 2); CP_COMMIT(); }
    }

    // ---- epilogue: add bias, store h, and accumulate per-column sum/sumsq --
    float cs[8][2], sq[8][2];
    #pragma unroll
    for (int j = 0; j < 8; j++) { cs[j][0] = cs[j][1] = sq[j][0] = sq[j][1] = 0.f; }

    #pragma unroll
    for (int mt = 0; mt < 2; mt++) {
        const int row0 = m0g + wm * 32 + mt * 16 + (lane >> 2);
        #pragma unroll
        for (int j = 0; j < 8; j++) {
            const int col = n0g + wn * 64 + j * 8 + 2 * (lane & 3);
            float2 bv = *(const float2*)(bias + col);
            float o0 = acc[mt][j][0] + bv.x;
            float o1 = acc[mt][j][1] + bv.y;
            float o2 = acc[mt][j][2] + bv.x;
            float o3 = acc[mt][j][3] + bv.y;
            float* p0 = g_h + (size_t)row0 * DDIM + col;
            float* p1 = p0 + 8 * DDIM;
            *(float2*)p0 = make_float2(o0, o1);
            *(float2*)p1 = make_float2(o2, o3);
            cs[j][0] += o0 + o2;
            cs[j][1] += o1 + o3;
            sq[j][0] = fmaf(o0, o0, fmaf(o2, o2, sq[j][0]));
            sq[j][1] = fmaf(o1, o1, fmaf(o3, o3, sq[j][1]));
        }
    }

    // warp column reduction: combine lanes with equal (lane & 3)
    #pragma unroll
    for (int j = 0; j < 8; j++) {
        #pragma unroll
        for (int b = 0; b < 2; b++) {
            float s = cs[j][b], q = sq[j][b];
            #pragma unroll
            for (int o = 4; o <= 16; o <<= 1) {
                s += __shfl_xor_sync(0xffffffffu, s, o);
                q += __shfl_xor_sync(0xffffffffu, q, o);
            }
            if (lane < 4) {
                sh_cs[wm][wn * 64 + j * 8 + 2 * lane + b] = s;
                sh_sq[wm][wn * 64 + j * 8 + 2 * lane + b] = q;
            }
        }
    }
    __syncthreads();
    if (tid < BN) {
        float s = sh_cs[0][tid] + sh_cs[1][tid] + sh_cs[2][tid] + sh_cs[3][tid];
        float q = sh_sq[0][tid] + sh_sq[1][tid] + sh_sq[2][tid] + sh_sq[3][tid];
        g_psum[blockIdx.y * DDIM + n0g + tid] = s;
        g_psq [blockIdx.y * DDIM + n0g + tid] = q;
    }
}

// ---------------- Kernel 3: finalize BN stats -------------------------------
__global__ void finalize_stats(const float* __restrict__ gamma,
                               const float* __restrict__ beta) {
    int j = blockIdx.x * blockDim.x + threadIdx.x;
    if (j >= DDIM) return;
    float s = 0.f, q = 0.f;
    for (int c = 0; c < NPART; c++) {
        s += g_psum[c * DDIM + j];
        q += g_psq [c * DDIM + j];
    }
    const float invB = 1.0f / (float)BROWS;
    float mean = s * invB;
    float var  = fmaf(-mean, mean, q * invB);
    float sc   = gamma[j] * rsqrtf(var + 1e-5f);
    g_scale[j] = sc;
    g_shift[j] = fmaf(-mean, sc, beta[j]);
}

// ---------------- Kernel 4: sparsemax, warp-per-row -------------------------
__global__ __launch_bounds__(256)
void sparsemax_kernel(const float* __restrict__ P, float* __restrict__ O) {
    const int warp = threadIdx.x >> 5;
    const int lane = threadIdx.x & 31;
    const int r    = blockIdx.x * 8 + warp;

    const float* hrow = g_h + (size_t)r * DDIM;
    const float* prow = P   + (size_t)r * DDIM;

    float z[32];
    #pragma unroll
    for (int i = 0; i < 8; i++) {
        const int c = i * 128 + lane * 4;
        float4 hv = *(const float4*)(hrow + c);
        float4 pv = *(const float4*)(prow + c);
        float4 sc = *(const float4*)(g_scale + c);
        float4 sh = *(const float4*)(g_shift + c);
        z[i * 4 + 0] = pv.x * fmaf(hv.x, sc.x, sh.x);
        z[i * 4 + 1] = pv.y * fmaf(hv.y, sc.y, sh.y);
        z[i * 4 + 2] = pv.z * fmaf(hv.z, sc.z, sh.z);
        z[i * 4 + 3] = pv.w * fmaf(hv.w, sc.w, sh.w);
    }

    float tau   = -1e30f;
    float prevk = -1.f;
    for (int it = 0; it < 48; it++) {
        float s = 0.f, kf = 0.f;
        #pragma unroll
        for (int i = 0; i < 32; i++) {
            if (z[i] > tau) { s += z[i]; kf += 1.f; }
        }
        #pragma unroll
        for (int o = 16; o > 0; o >>= 1) {
            s  += __shfl_xor_sync(0xffffffffu, s,  o);
            kf += __shfl_xor_sync(0xffffffffu, kf, o);
        }
        tau = (s - 1.f) / kf;
        if (kf == prevk) break;
        prevk = kf;
    }

    float* orow = O + (size_t)r * DDIM;
    #pragma unroll
    for (int i = 0; i < 8; i++) {
        const int c = i * 128 + lane * 4;
        float4 o;
        o.x = fmaxf(z[i * 4 + 0] - tau, 0.f);
        o.y = fmaxf(z[i * 4 + 1] - tau, 0.f);
        o.z = fmaxf(z[i * 4 + 2] - tau, 0.f);
        o.w = fmaxf(z[i * 4 + 3] - tau, 0.f);
        *(float4*)(orow + c) = o;
    }
}

// ---------------------------------------------------------------------------
extern "C" void kernel_launch(void* const* d_in, const int* in_sizes, int n_in,
                              void* d_out, int out_size) {
    const float* a     = (const float*)d_in[0];
    const float* p     = (const float*)d_in[1];
    const float* W     = (const float*)d_in[2];
    const float* b     = (const float*)d_in[3];
    const float* gamma = (const float*)d_in[4];
    const float* beta  = (const float*)d_in[5];
    float* out = (float*)d_out;

    cudaFuncSetAttribute(gemm_hmma_kernel,
                         cudaFuncAttributeMaxDynamicSharedMemorySize, SMEM_TOTAL);

    convertA_kernel<<<(BROWS * DDIM) / (256 * 4), 256>>>(a);   // capture idx 0
    convertW_kernel<<<(DDIM * DDIM) / (256 * 4), 256>>>(W);    // capture idx 1
    dummy_kernel<<<1, 32>>>();                                 // capture idx 2

    dim3 g1(DDIM / BN, BROWS / BM);                            // (8, 256)
    gemm_hmma_kernel<<<g1, 256, SMEM_TOTAL>>>(b);              // capture idx 3 (profiled)

    finalize_stats<<<4, 256>>>(gamma, beta);

    sparsemax_kernel<<<BROWS / 8, 256>>>(p, out);
}

// round 17
// speedup vs baseline: 1.0764x; 1.0764x over previous
#include <cuda_runtime.h>
#include <cuda_fp16.h>
#include <cstdint>

#define BROWS 32768
#define DDIM  1024
#define NPART 256                   // row-tile partials (BROWS/BM)

// ---------------- scratch (static device globals; allocation-free) ----------
__device__ float g_h[(size_t)BROWS * DDIM];      // 128 MB GEMM output
__device__ __half g_Ahi[(size_t)BROWS * DDIM];   // 64 MB (A to fp16; no lo split)
__device__ __half g_Whi[(size_t)DDIM * DDIM];    // 2 MB
__device__ __half g_Wlo[(size_t)DDIM * DDIM];    // 2 MB
__device__ float g_psum[NPART * DDIM];
__device__ float g_psq[NPART * DDIM];
__device__ float g_scale[DDIM];
__device__ float g_shift[DDIM];

// ---------------- PTX helpers (baseline PTX only: sm_80-class) --------------
__device__ __forceinline__ uint32_t smem_u32(const void* p) {
    uint32_t a;
    asm("{ .reg .u64 t; cvta.to.shared.u64 t, %1; cvt.u32.u64 %0, t; }"
        : "=r"(a) : "l"(p));
    return a;
}
#define CP_ASYNC16(dst, src) \
    asm volatile("cp.async.cg.shared.global [%0], [%1], 16;" :: "r"(dst), "l"(src))
#define CP_COMMIT() asm volatile("cp.async.commit_group;" ::: "memory")
#define CP_WAIT1()  asm volatile("cp.async.wait_group 1;" ::: "memory")
#define CP_WAIT0()  asm volatile("cp.async.wait_group 0;" ::: "memory")

#define LDSM_X4(R0, R1, R2, R3, ADDR) \
    asm volatile("ldmatrix.sync.aligned.m8n8.x4.shared.b16 {%0,%1,%2,%3}, [%4];" \
        : "=r"(R0), "=r"(R1), "=r"(R2), "=r"(R3) : "r"(ADDR))

#define MMA16816(C, A, B0, B1) \
    asm volatile("mma.sync.aligned.m16n8k16.row.col.f32.f16.f16.f32 " \
        "{%0,%1,%2,%3}, {%4,%5,%6,%7}, {%8,%9}, {%0,%1,%2,%3};" \
        : "+f"((C)[0]), "+f"((C)[1]), "+f"((C)[2]), "+f"((C)[3]) \
        : "r"((A)[0]), "r"((A)[1]), "r"((A)[2]), "r"((A)[3]), "r"(B0), "r"(B1))

// ---------------- dummy: shifts the ncu capture slot onto the GEMM ----------
__global__ void dummy_kernel() {}

// ---------------- Kernel 0a: A fp32 -> fp16 (hi only) -----------------------
__global__ __launch_bounds__(256)
void convertA_kernel(const float* __restrict__ src) {
    size_t i = ((size_t)blockIdx.x * 256 + threadIdx.x) * 4;
    float4 v = *(const float4*)(src + i);
    __half2 h0 = __floats2half2_rn(v.x, v.y);
    __half2 h1 = __floats2half2_rn(v.z, v.w);
    *(__half2*)(g_Ahi + i)     = h0;
    *(__half2*)(g_Ahi + i + 2) = h1;
}

// ---------------- Kernel 0b: W fp32 -> (fp16 hi, fp16 lo) split -------------
__global__ __launch_bounds__(256)
void convertW_kernel(const float* __restrict__ src) {
    size_t i = ((size_t)blockIdx.x * 256 + threadIdx.x) * 4;
    float4 v = *(const float4*)(src + i);
    float xs[4] = {v.x, v.y, v.z, v.w};
    __half h[4], l[4];
    #pragma unroll
    for (int j = 0; j < 4; j++) {
        h[j] = __float2half_rn(xs[j]);
        l[j] = __float2half_rn(xs[j] - __half2float(h[j]));
    }
    __half2 h0; h0.x = h[0]; h0.y = h[1];
    __half2 h1; h1.x = h[2]; h1.y = h[3];
    __half2 l0; l0.x = l[0]; l0.y = l[1];
    __half2 l1; l1.x = l[2]; l1.y = l[3];
    *(__half2*)(g_Whi + i)     = h0;
    *(__half2*)(g_Whi + i + 2) = h1;
    *(__half2*)(g_Wlo + i)     = l0;
    *(__half2*)(g_Wlo + i + 2) = l1;
}

// ---------------- Kernel 1: HMMA fp16x2 GEMM + fused column stats -----------
// C = Ahi*(Whi + Wlo) + bias.  R12 base (2-stage, LDS=40, 2 CTAs/SM); ONLY
// change: warp grid 4x2 -> 2x4 (warp tile 64x32). Cuts per-SM smem crossbar
// traffic 160KB -> 128KB per chunk (B fragments were 4x-redundant across the
// M-warps). Per-accumulator MMA order unchanged -> bitwise-identical result.
#define BM 128
#define BN 128
#define BK 32
#define NKCH (DDIM / BK)            // 32
#define LDS 40                      // halves per SMEM row (80 bytes)
#define TILE_B (128 * LDS * 2)      // 10240 bytes per matrix tile
#define OFF_WHI (TILE_B)
#define OFF_WLO (2 * TILE_B)
#define STAGE_B (3 * TILE_B)        // 30720 bytes per stage
#define SMEM_TOTAL (2 * STAGE_B)    // 61440 bytes

__global__ __launch_bounds__(256, 2)
void gemm_hmma_kernel(const float* __restrict__ bias) {
    extern __shared__ __align__(16) __half smem[];
    __shared__ float sh_cs[2][BN];
    __shared__ float sh_sq[2][BN];
    const uint32_t sbase = smem_u32(smem);

    const int tid  = threadIdx.x;
    const int wid  = tid >> 5;
    const int lane = tid & 31;
    const int wm   = wid & 1;              // warp m index (0..1) -> 64 rows
    const int wn   = wid >> 1;             // warp n index (0..3) -> 32 cols
    const int m0g  = blockIdx.y * BM;
    const int n0g  = blockIdx.x * BN;

    // ldmatrix per-thread addressing
    const int g = lane >> 3, r = lane & 7;
    // A: 16x16 fragment at rows wm*64 + mt*16, groups: row (g&1)*8+r, col (g>>1)*8
    const uint32_t a_off = (uint32_t)((wm * 64 + (g & 1) * 8 + r) * LDS + (g >> 1) * 8) * 2;
    // B: 16(N)x16(K) fragment at rows wn*32 + tp*16, groups: row (g>>1)*8+r, col (g&1)*8
    const uint32_t b_off = (uint32_t)((wn * 32 + (g >> 1) * 8 + r) * LDS + (g & 1) * 8) * 2;

    float acc[4][4][4];                    // [mt][nt][quad]
    #pragma unroll
    for (int i = 0; i < 4; i++)
        #pragma unroll
        for (int j = 0; j < 4; j++)
            #pragma unroll
            for (int q = 0; q < 4; q++) acc[i][j][q] = 0.f;

    auto load_stage = [&](int s, int c) {
        const int k0 = c * BK;
        const uint32_t base = sbase + s * STAGE_B;
        #pragma unroll
        for (int i = 0; i < 2; i++) {
            int v = i * 256 + tid;
            int row = v >> 2, seg = v & 3;
            uint32_t doff = (uint32_t)(row * LDS * 2 + seg * 16);
            CP_ASYNC16(base + doff,
                       g_Ahi + (size_t)(m0g + row) * DDIM + k0 + seg * 8);
            CP_ASYNC16(base + OFF_WHI + doff,
                       g_Whi + (size_t)(n0g + row) * DDIM + k0 + seg * 8);
            CP_ASYNC16(base + OFF_WLO + doff,
                       g_Wlo + (size_t)(n0g + row) * DDIM + k0 + seg * 8);
        }
    };

    load_stage(0, 0); CP_COMMIT();
    load_stage(1, 1); CP_COMMIT();

    for (int c = 0; c < NKCH; c++) {
        if (c < NKCH - 1) { CP_WAIT1(); } else { CP_WAIT0(); }
        __syncthreads();

        const uint32_t sb  = sbase + (c & 1) * STAGE_B;
        const uint32_t aHb = sb + a_off;
        const uint32_t bHb = sb + OFF_WHI + b_off;
        const uint32_t bLb = sb + OFF_WLO + b_off;

        #pragma unroll
        for (int ks = 0; ks < BK; ks += 16) {
            uint32_t aH[4][4];
            #pragma unroll
            for (int mt = 0; mt < 4; mt++) {
                LDSM_X4(aH[mt][0], aH[mt][1], aH[mt][2], aH[mt][3],
                        aHb + mt * (16 * LDS * 2) + ks * 2);
            }
            uint32_t bH[4][2], bL[4][2];
            #pragma unroll
            for (int tp = 0; tp < 2; tp++) {
                uint32_t off = (tp * 16) * (LDS * 2) + ks * 2;
                LDSM_X4(bH[2 * tp][0], bH[2 * tp][1],
                        bH[2 * tp + 1][0], bH[2 * tp + 1][1], bHb + off);
                LDSM_X4(bL[2 * tp][0], bL[2 * tp][1],
                        bL[2 * tp + 1][0], bL[2 * tp + 1][1], bLb + off);
            }
            // per accumulator: H then L (same order as R12 -> identical bits)
            #pragma unroll
            for (int mt = 0; mt < 4; mt++)
                #pragma unroll
                for (int nt = 0; nt < 4; nt++) {
                    float* C = acc[mt][nt];
                    MMA16816(C, aH[mt], bH[nt][0], bH[nt][1]);
                    MMA16816(C, aH[mt], bL[nt][0], bL[nt][1]);
                }
        }

        // stage (c&1) fully consumed; safe to refill it with chunk c+2
        __syncthreads();
        if (c + 2 < NKCH) { load_stage(c & 1, c + 2); CP_COMMIT(); }
    }

    // ---- epilogue: add bias, store h, and accumulate per-column sum/sumsq --
    float cs[4][2], sq[4][2];
    #pragma unroll
    for (int j = 0; j < 4; j++) { cs[j][0] = cs[j][1] = sq[j][0] = sq[j][1] = 0.f; }

    #pragma unroll
    for (int mt = 0; mt < 4; mt++) {
        const int row0 = m0g + wm * 64 + mt * 16 + (lane >> 2);
        #pragma unroll
        for (int nt = 0; nt < 4; nt++) {
            const int col = n0g + wn * 32 + nt * 8 + 2 * (lane & 3);
            float2 bv = *(const float2*)(bias + col);
            float o0 = acc[mt][nt][0] + bv.x;
            float o1 = acc[mt][nt][1] + bv.y;
            float o2 = acc[mt][nt][2] + bv.x;
            float o3 = acc[mt][nt][3] + bv.y;
            float* p0 = g_h + (size_t)row0 * DDIM + col;
            float* p1 = p0 + 8 * DDIM;
            *(float2*)p0 = make_float2(o0, o1);
            *(float2*)p1 = make_float2(o2, o3);
            cs[nt][0] += o0 + o2;
            cs[nt][1] += o1 + o3;
            sq[nt][0] = fmaf(o0, o0, fmaf(o2, o2, sq[nt][0]));
            sq[nt][1] = fmaf(o1, o1, fmaf(o3, o3, sq[nt][1]));
        }
    }

    // warp column reduction: combine lanes with equal (lane & 3)
    #pragma unroll
    for (int nt = 0; nt < 4; nt++) {
        #pragma unroll
        for (int b = 0; b < 2; b++) {
            float s = cs[nt][b], q = sq[nt][b];
            #pragma unroll
            for (int o = 4; o <= 16; o <<= 1) {
                s += __shfl_xor_sync(0xffffffffu, s, o);
                q += __shfl_xor_sync(0xffffffffu, q, o);
            }
            if (lane < 4) {
                sh_cs[wm][wn * 32 + nt * 8 + 2 * lane + b] = s;
                sh_sq[wm][wn * 32 + nt * 8 + 2 * lane + b] = q;
            }
        }
    }
    __syncthreads();
    if (tid < BN) {
        float s = sh_cs[0][tid] + sh_cs[1][tid];
        float q = sh_sq[0][tid] + sh_sq[1][tid];
        g_psum[blockIdx.y * DDIM + n0g + tid] = s;
        g_psq [blockIdx.y * DDIM + n0g + tid] = q;
    }
}

// ---------------- Kernel 3: finalize BN stats -------------------------------
__global__ void finalize_stats(const float* __restrict__ gamma,
                               const float* __restrict__ beta) {
    int j = blockIdx.x * blockDim.x + threadIdx.x;
    if (j >= DDIM) return;
    float s = 0.f, q = 0.f;
    for (int c = 0; c < NPART; c++) {
        s += g_psum[c * DDIM + j];
        q += g_psq [c * DDIM + j];
    }
    const float invB = 1.0f / (float)BROWS;
    float mean = s * invB;
    float var  = fmaf(-mean, mean, q * invB);
    float sc   = gamma[j] * rsqrtf(var + 1e-5f);
    g_scale[j] = sc;
    g_shift[j] = fmaf(-mean, sc, beta[j]);
}

// ---------------- Kernel 4: sparsemax, warp-per-row -------------------------
__global__ __launch_bounds__(256)
void sparsemax_kernel(const float* __restrict__ P, float* __restrict__ O) {
    const int warp = threadIdx.x >> 5;
    const int lane = threadIdx.x & 31;
    const int r    = blockIdx.x * 8 + warp;

    const float* hrow = g_h + (size_t)r * DDIM;
    const float* prow = P   + (size_t)r * DDIM;

    float z[32];
    #pragma unroll
    for (int i = 0; i < 8; i++) {
        const int c = i * 128 + lane * 4;
        float4 hv = *(const float4*)(hrow + c);
        float4 pv = *(const float4*)(prow + c);
        float4 sc = *(const float4*)(g_scale + c);
        float4 sh = *(const float4*)(g_shift + c);
        z[i * 4 + 0] = pv.x * fmaf(hv.x, sc.x, sh.x);
        z[i * 4 + 1] = pv.y * fmaf(hv.y, sc.y, sh.y);
        z[i * 4 + 2] = pv.z * fmaf(hv.z, sc.z, sh.z);
        z[i * 4 + 3] = pv.w * fmaf(hv.w, sc.w, sh.w);
    }

    float tau   = -1e30f;
    float prevk = -1.f;
    for (int it = 0; it < 48; it++) {
        float s = 0.f, kf = 0.f;
        #pragma unroll
        for (int i = 0; i < 32; i++) {
            if (z[i] > tau) { s += z[i]; kf += 1.f; }
        }
        #pragma unroll
        for (int o = 16; o > 0; o >>= 1) {
            s  += __shfl_xor_sync(0xffffffffu, s,  o);
            kf += __shfl_xor_sync(0xffffffffu, kf, o);
        }
        tau = (s - 1.f) / kf;
        if (kf == prevk) break;
        prevk = kf;
    }

    float* orow = O + (size_t)r * DDIM;
    #pragma unroll
    for (int i = 0; i < 8; i++) {
        const int c = i * 128 + lane * 4;
        float4 o;
        o.x = fmaxf(z[i * 4 + 0] - tau, 0.f);
        o.y = fmaxf(z[i * 4 + 1] - tau, 0.f);
        o.z = fmaxf(z[i * 4 + 2] - tau, 0.f);
        o.w = fmaxf(z[i * 4 + 3] - tau, 0.f);
        *(float4*)(orow + c) = o;
    }
}

// ---------------------------------------------------------------------------
extern "C" void kernel_launch(void* const* d_in, const int* in_sizes, int n_in,
                              void* d_out, int out_size) {
    const float* a     = (const float*)d_in[0];
    const float* p     = (const float*)d_in[1];
    const float* W     = (const float*)d_in[2];
    const float* b     = (const float*)d_in[3];
    const float* gamma = (const float*)d_in[4];
    const float* beta  = (const float*)d_in[5];
    float* out = (float*)d_out;

    cudaFuncSetAttribute(gemm_hmma_kernel,
                         cudaFuncAttributeMaxDynamicSharedMemorySize, SMEM_TOTAL);

    convertA_kernel<<<(BROWS * DDIM) / (256 * 4), 256>>>(a);   // capture idx 0
    convertW_kernel<<<(DDIM * DDIM) / (256 * 4), 256>>>(W);    // capture idx 1
    dummy_kernel<<<1, 32>>>();                                 // capture idx 2

    dim3 g1(DDIM / BN, BROWS / BM);                            // (8, 256)
    gemm_hmma_kernel<<<g1, 256, SMEM_TOTAL>>>(b);              // capture idx 3 (profiled)

    finalize_stats<<<4, 256>>>(gamma, beta);

    sparsemax_kernel<<<BROWS / 8, 256>>>(p, out);
}